// round 7
// baseline (speedup 1.0000x reference)
#include <cuda_runtime.h>

// Integrate-and-fire scan fused with per-timestep 64x512 transpose.
//   v += x[t]; if (v > 2.0f) { spike[t] = 1; v = 0; }  (membrane reset at t=100)
//
// R4: barrier-free, smem-free. Each thread owns 4 CONSECUTIVE h at fixed wc
// (= one output float4), so the transpose is thread-local:
//  - loads: warp = 32 consecutive wc, 4 scalar LDGs (one per h row), each a
//    full 128B line -> minimal load wavefronts (was 4x ideal in R2/R3).
//  - stores: one STG.128 per thread per t; half-sector writes merge in L2
//    (neighbor warp writes the adjacent 16B concurrently).
//  - 16 front-batched prefetch loads per thread (next 4-timestep group)
//    give ~64B/thread in flight with no barrier ever exposing latency.

namespace {
constexpr int kH     = 64;
constexpr int kWC    = 512;                    // W*C
constexpr int kChunk = 100;
constexpr int kNPB   = kH * kWC;               // 32768 neurons / batch
constexpr long long kBS = 200LL * kNPB;        // batch stride (elements)
constexpr int kGroup = 4;                      // timesteps per unrolled group
constexpr int kNG    = kChunk / kGroup;        // 25
constexpr float kTh  = 2.0f;
}

__global__ void __launch_bounds__(256)
integrator_kernel(const float* __restrict__ in, float* __restrict__ out) {
    const int tid  = threadIdx.x;
    const int lane = tid & 31;                 // wc within tile (coalesced)
    const int hq   = tid >> 5;                 // 0..7: h quad within tile
    const int wc   = blockIdx.x * 32 + lane;
    const int hb   = blockIdx.y * 32 + hq * 4; // first of 4 consecutive h
    const int b    = blockIdx.z >> 1;
    const int t0   = (blockIdx.z & 1) * kChunk;

    const long long base = b * kBS + (long long)t0 * kNPB;
    const float* __restrict__ pin = in + base + (long long)hb * kWC + wc;
    float*       __restrict__ pout = out + base + (long long)wc * kH + hb;

    float v0 = 0.f, v1 = 0.f, v2 = 0.f, v3 = 0.f;

    float nxt[kGroup][4];
#pragma unroll
    for (int g = 0; g < kGroup; ++g)
#pragma unroll
        for (int j = 0; j < 4; ++j)
            nxt[g][j] = pin[(long long)g * kNPB + j * kWC];

    for (int gi = 0; gi < kNG; ++gi) {
        float cur[kGroup][4];
#pragma unroll
        for (int g = 0; g < kGroup; ++g)
#pragma unroll
            for (int j = 0; j < 4; ++j) cur[g][j] = nxt[g][j];

        // Front-batched prefetch of the next group's 16 loads: they drain
        // behind this group's compute + 4 stores. No barriers anywhere.
        if (gi + 1 < kNG) {
            const float* pn = pin + (long long)(gi + 1) * kGroup * kNPB;
#pragma unroll
            for (int g = 0; g < kGroup; ++g)
#pragma unroll
                for (int j = 0; j < 4; ++j)
                    nxt[g][j] = pn[(long long)g * kNPB + j * kWC];
        }

#pragma unroll
        for (int g = 0; g < kGroup; ++g) {
            float4 o;
            v0 += cur[g][0]; o.x = (v0 > kTh) ? 1.f : 0.f; v0 = (v0 > kTh) ? 0.f : v0;
            v1 += cur[g][1]; o.y = (v1 > kTh) ? 1.f : 0.f; v1 = (v1 > kTh) ? 0.f : v1;
            v2 += cur[g][2]; o.z = (v2 > kTh) ? 1.f : 0.f; v2 = (v2 > kTh) ? 0.f : v2;
            v3 += cur[g][3]; o.w = (v3 > kTh) ? 1.f : 0.f; v3 = (v3 > kTh) ? 0.f : v3;
            *reinterpret_cast<float4*>(
                pout + (long long)(gi * kGroup + g) * kNPB) = o;
        }
    }
}

extern "C" void kernel_launch(void* const* d_in, const int* in_sizes, int n_in,
                              void* d_out, int out_size) {
    (void)in_sizes; (void)n_in; (void)out_size;
    const float* in = (const float*)d_in[0];
    float* out = (float*)d_out;
    dim3 grid(kWC / 32, kH / 32, 4 * 2);   // 16 x 2 x 8 = 256 blocks
    integrator_kernel<<<grid, 256>>>(in, out);
}

// round 9
// speedup vs baseline: 2.0468x; 2.0468x over previous
#include <cuda_runtime.h>

// Integrate-and-fire scan fused with per-timestep 64x512 transpose.
//   v += x[t]; if (v > 2.0f) { spike[t] = 1; v = 0; }  (membrane reset at t=100)
//
// R6 = R5 with the smem alignment bug fixed: global traffic stays LDG.64 /
// STG.64 (warp = 2 full 128B lines each, wavefront-ideal both directions),
// but smem transpose traffic is scalar STS.32/LDS.32 (pad-33 row stride is
// 132B, not 8B-aligned -> float2 smem ops trapped in R5). Scalar pattern is
// bank-conflict-free: half-warps land on opposite bank parities.
// Double-buffered smem -> ONE barrier per 4-timestep group (25 total).
// 512 threads/block, 2 neurons/thread, 256 blocks.

namespace {
constexpr int kH     = 64;
constexpr int kWC    = 512;                      // W*C
constexpr int kChunk = 100;
constexpr int kNPB   = kH * kWC;                 // 32768 neurons / batch
constexpr long long kBS = 200LL * kNPB;          // batch stride (elements)
constexpr int kGroup = 4;                        // timesteps per barrier
constexpr int kNG    = kChunk / kGroup;          // 25
constexpr float kTh  = 2.0f;
}

__global__ void __launch_bounds__(512)
integrator_kernel(const float* __restrict__ in, float* __restrict__ out) {
    __shared__ float sm[2][kGroup][32][33];      // [buf][t][h-row][wc], pad 33

    const int tid = threadIdx.x;
    const int row = tid >> 4;                    // 0..31
    const int p   = tid & 15;                    // 0..15
    const int sh2 = p * 2;
    const int wc0 = blockIdx.x * 32;
    const int h0  = blockIdx.y * 32;
    const int b   = blockIdx.z >> 1;
    const int t0  = (blockIdx.z & 1) * kChunk;

    const long long base = b * kBS + (long long)t0 * kNPB;

    // Load: thread owns neurons (h0+row, wc0+2p, wc0+2p+1).
    // Warp LDG.64 = 2 h-rows x 16 float2 = 2 full 128B lines (ideal).
    const float* __restrict__ pin =
        in + base + (long long)(h0 + row) * kWC + wc0 + sh2;

    // Store: thread writes float2 of h at wc = wc0+row.
    // Warp STG.64 = 2 wc-rows x 16 float2 = 2 full 128B lines (ideal).
    float* __restrict__ pout =
        out + base + (long long)(wc0 + row) * kH + h0 + sh2;

    float v0 = 0.f, v1 = 0.f;

    float2 nxt[kGroup];
#pragma unroll
    for (int g = 0; g < kGroup; ++g)
        nxt[g] = *reinterpret_cast<const float2*>(pin + (long long)g * kNPB);

    for (int gi = 0; gi < kNG; ++gi) {
        const int pb = gi & 1;

        float2 cur[kGroup];
#pragma unroll
        for (int g = 0; g < kGroup; ++g) cur[g] = nxt[g];

        // Prefetch next group's 4 independent LDG.64s; they drain behind
        // this group's compute + barrier + store phase.
        if (gi + 1 < kNG) {
            const float* pn = pin + (long long)(gi + 1) * kGroup * kNPB;
#pragma unroll
            for (int g = 0; g < kGroup; ++g)
                nxt[g] = *reinterpret_cast<const float2*>(pn + (long long)g * kNPB);
        }

#pragma unroll
        for (int g = 0; g < kGroup; ++g) {
            float s0, s1;
            v0 += cur[g].x; s0 = (v0 > kTh) ? 1.f : 0.f; v0 = (v0 > kTh) ? 0.f : v0;
            v1 += cur[g].y; s1 = (v1 > kTh) ? 1.f : 0.f; v1 = (v1 > kTh) ? 0.f : v1;
            // Scalar STS: banks (row + 2p) / (row + 2p + 1); half-warps on
            // opposite parities -> 32 distinct banks per instruction.
            sm[pb][g][row][sh2 + 0] = s0;
            sm[pb][g][row][sh2 + 1] = s1;
        }
        __syncthreads();   // single barrier; double buffer protects reuse

#pragma unroll
        for (int g = 0; g < kGroup; ++g) {
            float2 o;
            o.x = sm[pb][g][sh2 + 0][row];   // bank (2p + row): conflict-free
            o.y = sm[pb][g][sh2 + 1][row];   // bank (2p + 1 + row)
            *reinterpret_cast<float2*>(
                pout + (long long)(gi * kGroup + g) * kNPB) = o;
        }
    }
}

extern "C" void kernel_launch(void* const* d_in, const int* in_sizes, int n_in,
                              void* d_out, int out_size) {
    (void)in_sizes; (void)n_in; (void)out_size;
    const float* in = (const float*)d_in[0];
    float* out = (float*)d_out;
    dim3 grid(kWC / 32, kH / 32, 4 * 2);   // 16 x 2 x 8 = 256 blocks x 512 thr
    integrator_kernel<<<grid, 512>>>(in, out);
}

// round 11
// speedup vs baseline: 2.1559x; 1.0533x over previous
#include <cuda_runtime.h>

// Integrate-and-fire scan fused with per-timestep 64x512 transpose.
//   v += x[t]; if (v > 2.0f) { spike[t] = 1; v = 0; }  (membrane reset at t=100)
//
// R7 = R6 (wavefront-ideal 32x32 tile, LDG.64/STG.64 = 2 full 128B lines per
// warp both directions, double-buffered smem -> 1 barrier per 4-timestep
// group, scalar bank-conflict-free STS/LDS, 512 thr x 2 neurons) plus
// PREFETCH DISTANCE 2: two register queues q0/q1 hold 8 outstanding LDG.64
// per thread (64B in flight), so even SMs holding a single CTA (40 of 148 at
// this 256-CTA grid) have ~32KB of read bytes in flight -- above the
// BW*latency product. Loads are consumed two group-periods after issue.

namespace {
constexpr int kH     = 64;
constexpr int kWC    = 512;                      // W*C
constexpr int kChunk = 100;
constexpr int kNPB   = kH * kWC;                 // 32768 neurons / batch
constexpr long long kBS = 200LL * kNPB;          // batch stride (elements)
constexpr int kGroup = 4;                        // timesteps per barrier
constexpr int kNG    = kChunk / kGroup;          // 25
constexpr float kTh  = 2.0f;
}

__global__ void __launch_bounds__(512)
integrator_kernel(const float* __restrict__ in, float* __restrict__ out) {
    __shared__ float sm[2][kGroup][32][33];      // [buf][t][h-row][wc], pad 33

    const int tid = threadIdx.x;
    const int row = tid >> 4;                    // 0..31
    const int p   = tid & 15;                    // 0..15
    const int sh2 = p * 2;
    const int wc0 = blockIdx.x * 32;
    const int h0  = blockIdx.y * 32;
    const int b   = blockIdx.z >> 1;
    const int t0  = (blockIdx.z & 1) * kChunk;

    const long long base = b * kBS + (long long)t0 * kNPB;

    // Load: thread owns neurons (h0+row, wc0+2p, wc0+2p+1).
    const float* __restrict__ pin =
        in + base + (long long)(h0 + row) * kWC + wc0 + sh2;
    // Store: thread writes float2 of h at wc = wc0+row.
    float* __restrict__ pout =
        out + base + (long long)(wc0 + row) * kH + h0 + sh2;

    float v0 = 0.f, v1 = 0.f;

    float2 q0[kGroup], q1[kGroup];
#pragma unroll
    for (int g = 0; g < kGroup; ++g) {
        q0[g] = *reinterpret_cast<const float2*>(pin + (long long)(0 * kGroup + g) * kNPB);
        q1[g] = *reinterpret_cast<const float2*>(pin + (long long)(1 * kGroup + g) * kNPB);
    }

    // One group: consume q, refill q with loads for group (gi+2), store spikes.
    auto process = [&](int gi, float2 (&q)[kGroup]) {
        const int pb = gi & 1;
#pragma unroll
        for (int g = 0; g < kGroup; ++g) {
            float s0, s1;
            v0 += q[g].x; s0 = (v0 > kTh) ? 1.f : 0.f; v0 = (v0 > kTh) ? 0.f : v0;
            v1 += q[g].y; s1 = (v1 > kTh) ? 1.f : 0.f; v1 = (v1 > kTh) ? 0.f : v1;
            // banks (row + 2p) / (row + 2p + 1): half-warps on opposite
            // parities -> 32 distinct banks, conflict-free.
            sm[pb][g][row][sh2 + 0] = s0;
            sm[pb][g][row][sh2 + 1] = s1;
        }
        // Refill queue for group gi+2 (consumed two group-periods from now).
        if (gi + 2 < kNG) {
            const float* pn = pin + (long long)(gi + 2) * kGroup * kNPB;
#pragma unroll
            for (int g = 0; g < kGroup; ++g)
                q[g] = *reinterpret_cast<const float2*>(pn + (long long)g * kNPB);
        }
        __syncthreads();   // single barrier; double buffer protects reuse
#pragma unroll
        for (int g = 0; g < kGroup; ++g) {
            float2 o;
            o.x = sm[pb][g][sh2 + 0][row];   // bank (2p + row): conflict-free
            o.y = sm[pb][g][sh2 + 1][row];
            *reinterpret_cast<float2*>(
                pout + (long long)(gi * kGroup + g) * kNPB) = o;
        }
    };

#pragma unroll 1
    for (int gi = 0; gi < kNG - 1; gi += 2) {    // 12 pairs: groups 0..23
        process(gi,     q0);
        process(gi + 1, q1);
    }
    process(kNG - 1, q0);                        // group 24

}

extern "C" void kernel_launch(void* const* d_in, const int* in_sizes, int n_in,
                              void* d_out, int out_size) {
    (void)in_sizes; (void)n_in; (void)out_size;
    const float* in = (const float*)d_in[0];
    float* out = (float*)d_out;
    dim3 grid(kWC / 32, kH / 32, 4 * 2);   // 16 x 2 x 8 = 256 blocks x 512 thr
    integrator_kernel<<<grid, 512>>>(in, out);
}